// round 14
// baseline (speedup 1.0000x reference)
#include <cuda_runtime.h>
#include <cuda_fp16.h>
#include <cstdint>

#define NCH1 21                 // K1 = 1283 -> 21 chunks of 64
#define NCH2 4                  // K2 = 256  -> 4 chunks of 64
#define KPAD1 1344
#define INV_CAT (1.0f/1283.0f)

// smem (bytes): A stage s at s*18432 (128 rows x 72 halves, stride 144B)
//               B stage s at 36864 + s*17408 (64 rows x 136 halves, stride 272B)
#define A_ST   18432
#define B_BASE 36864
#define B_ST   17408
#define SMEM_DYN (B_BASE + 2*B_ST)   // 71680 ; x3 CTAs = 215 KB/SM

// ---------------- scratch (no cudaMalloc allowed) ----------------
__device__ __align__(16) __half g_y1[65536u*256];
__device__ __align__(16) __half g_B1h[KPAD1*256];
__device__ __align__(16) __half g_B2h[256*256];
__device__ float g_v[256];
__device__ float g_u[256];
__device__ float g_part[16*512];

// ---------------- helpers ----------------
__device__ __forceinline__ uint32_t smem_u32(const void* p) {
    uint32_t a;
    asm("{ .reg .u64 t; cvta.to.shared.u64 t, %1; cvt.u32.u64 %0, t; }" : "=r"(a) : "l"(p));
    return a;
}
#define CP_A16(dst, src) \
    asm volatile("cp.async.cg.shared.global [%0], [%1], 16;" :: "r"(dst), "l"(src) : "memory")
#define CP_COMMIT() asm volatile("cp.async.commit_group;" ::: "memory")
#define CP_WAIT0()  asm volatile("cp.async.wait_group 0;" ::: "memory")

__device__ __forceinline__ void ldsm_x4(uint32_t* f, uint32_t a) {
    asm volatile("ldmatrix.sync.aligned.m8n8.x4.shared.b16 {%0,%1,%2,%3}, [%4];"
                 : "=r"(f[0]), "=r"(f[1]), "=r"(f[2]), "=r"(f[3]) : "r"(a));
}
__device__ __forceinline__ void ldsm_x4t(uint32_t* f, uint32_t a) {
    asm volatile("ldmatrix.sync.aligned.m8n8.x4.trans.shared.b16 {%0,%1,%2,%3}, [%4];"
                 : "=r"(f[0]), "=r"(f[1]), "=r"(f[2]), "=r"(f[3]) : "r"(a));
}
__device__ __forceinline__ void mma16816(float* c, const uint32_t* a, uint32_t b0, uint32_t b1) {
    asm volatile("mma.sync.aligned.m16n8k16.row.col.f32.f16.f16.f32 "
                 "{%0,%1,%2,%3}, {%4,%5,%6,%7}, {%8,%9}, {%0,%1,%2,%3};"
                 : "+f"(c[0]), "+f"(c[1]), "+f"(c[2]), "+f"(c[3])
                 : "r"(a[0]), "r"(a[1]), "r"(a[2]), "r"(a[3]), "r"(b0), "r"(b1));
}
__device__ __forceinline__ float gelu_f(float x) {
    return 0.5f * x * (1.0f + erff(x * 0.70710678118654752f));
}
__device__ __forceinline__ uint32_t pack_h2(float a, float b) {
    __half2 h = __floats2half2_rn(a, b);
    return *reinterpret_cast<uint32_t*>(&h);
}

// one k-step (K=16): 4 A-ldsm + 4 B-ldsm -> 32 MMAs (warptile 64M x 64N).
// B fetched in two halves to bound live registers.
__device__ __forceinline__ void mma_kstep(float (&acc)[4][8][4],
                                          uint32_t aB, uint32_t bB, int kk,
                                          int m0w, int n0w, int lr, int lc) {
    uint32_t ah[4][4];
#pragma unroll
    for (int mi = 0; mi < 4; mi++) {
        uint32_t off = (uint32_t)(((m0w + mi * 16 + lr) * 72 + kk + lc) * 2);
        ldsm_x4(ah[mi], aB + off);
    }
#pragma unroll
    for (int h = 0; h < 2; h++) {
        uint32_t b[2][4];
#pragma unroll
        for (int j = 0; j < 2; j++) {
            int np = h * 2 + j;
            uint32_t boff = (uint32_t)(((kk + lr) * 136 + n0w + np * 16 + lc) * 2);
            ldsm_x4t(b[j], bB + boff);
        }
#pragma unroll
        for (int j = 0; j < 2; j++) {
            int np = h * 2 + j;
#pragma unroll
            for (int mi = 0; mi < 4; mi++) {
                mma16816(acc[mi][np * 2],     ah[mi], b[j][0], b[j][1]);
                mma16816(acc[mi][np * 2 + 1], ah[mi], b[j][2], b[j][3]);
            }
        }
    }
}

// B chunk copy: 64 rows x 256B (128 fp16 cols), dst stride 272B; 128 threads
__device__ __forceinline__ void cpB(uint32_t smBase, int s, const __half* src, int t) {
    int row = t >> 1, cb = (t & 1) * 128;
    uint32_t d = smBase + B_BASE + s * B_ST + (uint32_t)(row * 272 + cb);
    const char* sp = (const char*)src + row * 512 + cb;
#pragma unroll
    for (int j = 0; j < 8; j++) CP_A16(d + j * 16, sp + j * 16);
}

// load 16 fp32 cols at absolute col c0 for row r
__device__ __forceinline__ void load_x16(const float* const* seg,
                                         const float* rel, const float* vis,
                                         int r, int c0, float* x) {
    if (c0 < 1280) {
        const float* p = seg[c0 >> 8] + (c0 & 255);
#pragma unroll
        for (int j = 0; j < 4; j++) {
            float4 f = ((const float4*)p)[j];
            x[4 * j] = f.x; x[4 * j + 1] = f.y; x[4 * j + 2] = f.z; x[4 * j + 3] = f.w;
        }
    } else {
#pragma unroll
        for (int j = 0; j < 16; j++) x[j] = 0.f;
        if (c0 == 1280) {
            x[0] = rel[(size_t)r * 2];
            x[1] = rel[(size_t)r * 2 + 1];
            x[2] = vis[r];
        }
    }
}

// pack 16 cols -> 8 half2, store into A stage s at (row, part q)
__device__ __forceinline__ void packA(char* sm, int s, int row, int q,
                                      const float* x, float& sum, float& ss) {
    uint32_t hp[8];
#pragma unroll
    for (int j = 0; j < 8; j++) {
        float a = x[2 * j], b = x[2 * j + 1];
        sum += a + b; ss = fmaf(a, a, ss); ss = fmaf(b, b, ss);
        hp[j] = pack_h2(a, b);
    }
    char* da = sm + s * A_ST + (uint32_t)(row * 144 + q * 32);
    ((uint4*)da)[0] = make_uint4(hp[0], hp[1], hp[2], hp[3]);
    ((uint4*)da)[1] = make_uint4(hp[4], hp[5], hp[6], hp[7]);
}

// ---------------- prep kernels (3 launches before gemm1) ----------------
__global__ void prep_w1(const float* __restrict__ W1, const float* __restrict__ gamma) {
    int c = blockIdx.x, d = threadIdx.x;
    float w = (c < 1283) ? W1[(size_t)c * 256 + d] * gamma[c] : 0.0f;
    g_B1h[(size_t)c * 256 + d] = __float2half_rn(w);
}
__global__ void prep_vu_part(const float* __restrict__ W1, const float* __restrict__ gamma,
                             const float* __restrict__ beta) {
    int b = blockIdx.x, d = threadIdx.x;
    int c0 = b * 81, c1 = c0 + 81; if (c1 > 1283) c1 = 1283;
    float v = 0.f, u = 0.f;
    for (int c = c0; c < c1; c++) {
        float w = W1[(size_t)c * 256 + d];
        v += gamma[c] * w;
        u += beta[c] * w;
    }
    g_part[b * 512 + d] = v;
    g_part[b * 512 + 256 + d] = u;
}
// W2 convert + v/u final reduce in one launch (block 256 does the reduce)
__global__ void prep_w2_vu(const float* __restrict__ W2, const float* __restrict__ b1) {
    int d = threadIdx.x;
    if (blockIdx.x < 256) {
        int c = blockIdx.x;
        g_B2h[(size_t)c * 256 + d] = __float2half_rn(W2[(size_t)c * 256 + d]);
    } else {
        float v = 0.f, u = 0.f;
#pragma unroll
        for (int b = 0; b < 16; b++) {
            v += g_part[b * 512 + d];
            u += g_part[b * 512 + 256 + d];
        }
        g_v[d] = v;
        g_u[d] = u + b1[d];
    }
}

// ---------------- GEMM1: raw concat-x @ W1g, LN-folded epilogue + GELU -> g_y1 ----------------
__global__ __launch_bounds__(128, 3) void gemm1(
    const float* __restrict__ pt, const float* __restrict__ sh,
    const float* __restrict__ dyn, const float* __restrict__ sem,
    const float* __restrict__ pit, const float* __restrict__ rel,
    const float* __restrict__ vis) {
    extern __shared__ char sm[];
    __shared__ float s_sum[128], s_ss[128];

    int t = threadIdx.x, l = t & 31, wid = t >> 5;
    int m0w = (wid & 1) * 64, n0w = (wid >> 1) * 64;
    int lr = l & 15, lc = (l & 16) >> 1;
    int d0 = blockIdx.x * 128, rowBase = blockIdx.y * 128;
    int row = t;                      // each thread stages one full row
    int r = rowBase + row;
    int b_ = r >> 14, m_ = (r >> 6) & 255, h_ = r & 63;
    const float* seg[5] = { pt + (size_t)((b_ << 8) + m_) * 256,
                            sh + (size_t)((b_ << 6) + h_) * 256,
                            dyn + (size_t)r * 256,
                            sem + (size_t)r * 256,
                            pit + (size_t)r * 256 };
    uint32_t base = smem_u32(sm);

    float acc[4][8][4];
#pragma unroll
    for (int i = 0; i < 4; i++)
#pragma unroll
        for (int j = 0; j < 8; j++)
#pragma unroll
            for (int k = 0; k < 4; k++) acc[i][j][k] = 0.f;
    float sum = 0.f, ss = 0.f;
    float x[16];

    // ---- prologue: stage chunk 0 ----
    cpB(base, 0, g_B1h + d0, t);
    CP_COMMIT();
#pragma unroll
    for (int q = 0; q < 4; q++) {
        load_x16(seg, rel, vis, r, q * 16, x);
        packA(sm, 0, row, q, x, sum, ss);
    }
    CP_WAIT0();
    __syncthreads();

    for (int c = 0; c < NCH1; c++) {
        int s = c & 1, ns = s ^ 1;
        bool more = (c + 1 < NCH1);
        int nc = (c + 1) * 64;
        uint32_t aB = base + s * A_ST, bB = base + B_BASE + s * B_ST;
        if (more) {
            load_x16(seg, rel, vis, r, nc, x);
            cpB(base, ns, g_B1h + (size_t)(c + 1) * 16384 + d0, t);
            CP_COMMIT();
        }
        mma_kstep(acc, aB, bB, 0, m0w, n0w, lr, lc);
        if (more) { packA(sm, ns, row, 0, x, sum, ss); load_x16(seg, rel, vis, r, nc + 16, x); }
        mma_kstep(acc, aB, bB, 16, m0w, n0w, lr, lc);
        if (more) { packA(sm, ns, row, 1, x, sum, ss); load_x16(seg, rel, vis, r, nc + 32, x); }
        mma_kstep(acc, aB, bB, 32, m0w, n0w, lr, lc);
        if (more) { packA(sm, ns, row, 2, x, sum, ss); load_x16(seg, rel, vis, r, nc + 48, x); }
        mma_kstep(acc, aB, bB, 48, m0w, n0w, lr, lc);
        if (more) packA(sm, ns, row, 3, x, sum, ss);
        CP_WAIT0();
        __syncthreads();
    }

    // ---- row stats: each thread owns its row entirely ----
    s_sum[row] = sum; s_ss[row] = ss;
    __syncthreads();

    // ---- epilogue: LN correction + GELU -> fp16 y1 ----
    int rq = l >> 2, cq = (l & 3) * 2;
#pragma unroll
    for (int mi = 0; mi < 4; mi++) {
        int rl = m0w + mi * 16 + rq;
        float mu0 = s_sum[rl] * INV_CAT;
        float rs0 = rsqrtf(fmaf(-mu0, mu0, s_ss[rl] * INV_CAT) + 1e-5f);
        float mu1 = s_sum[rl + 8] * INV_CAT;
        float rs1 = rsqrtf(fmaf(-mu1, mu1, s_ss[rl + 8] * INV_CAT) + 1e-5f);
        int grow = rowBase + rl;
#pragma unroll
        for (int ni = 0; ni < 8; ni++) {
            int gcol = d0 + n0w + ni * 8 + cq;
            float v0 = __ldg(&g_v[gcol]), v1 = __ldg(&g_v[gcol + 1]);
            float u0 = __ldg(&g_u[gcol]), u1 = __ldg(&g_u[gcol + 1]);
            float* a = acc[mi][ni];
            float y0 = gelu_f(fmaf(rs0, a[0] - mu0 * v0, u0));
            float y1 = gelu_f(fmaf(rs0, a[1] - mu0 * v1, u1));
            float y2 = gelu_f(fmaf(rs1, a[2] - mu1 * v0, u0));
            float y3 = gelu_f(fmaf(rs1, a[3] - mu1 * v1, u1));
            *(uint32_t*)&g_y1[(size_t)grow * 256 + gcol] = pack_h2(y0, y1);
            *(uint32_t*)&g_y1[(size_t)(grow + 8) * 256 + gcol] = pack_h2(y2, y3);
        }
    }
}

// ---------------- GEMM2: y1 @ W2 + b2, GELU -> out ----------------
__global__ __launch_bounds__(128, 3) void gemm2(const float* __restrict__ b2,
                                                float* __restrict__ out) {
    extern __shared__ char sm[];
    int t = threadIdx.x, l = t & 31, wid = t >> 5;
    int m0w = (wid & 1) * 64, n0w = (wid >> 1) * 64;
    int lr = l & 15, lc = (l & 16) >> 1;
    int d0 = blockIdx.x * 128, rowBase = blockIdx.y * 128;
    int row = t;
    int r = rowBase + row;
    uint32_t base = smem_u32(sm);

    float acc[4][8][4];
#pragma unroll
    for (int i = 0; i < 4; i++)
#pragma unroll
        for (int j = 0; j < 8; j++)
#pragma unroll
            for (int k = 0; k < 4; k++) acc[i][j][k] = 0.f;

    const char* ybase = (const char*)(g_y1 + (size_t)r * 256);
    uint32_t adst = base + (uint32_t)(row * 144);

    // prologue: stage chunk 0 (A row = 128B via cp.async)
#pragma unroll
    for (int j = 0; j < 8; j++) CP_A16(adst + j * 16, ybase + j * 16);
    cpB(base, 0, g_B2h + d0, t);
    CP_COMMIT();
    CP_WAIT0();
    __syncthreads();

    for (int c = 0; c < NCH2; c++) {
        int s = c & 1, ns = s ^ 1;
        bool more = (c + 1 < NCH2);
        uint32_t aB = base + s * A_ST, bB = base + B_BASE + s * B_ST;
        if (more) {
            const char* ysrc = ybase + (size_t)(c + 1) * 128;
            uint32_t ad = adst + ns * A_ST;
#pragma unroll
            for (int j = 0; j < 8; j++) CP_A16(ad + j * 16, ysrc + j * 16);
            cpB(base, ns, g_B2h + (size_t)(c + 1) * 16384 + d0, t);
            CP_COMMIT();
        }
        mma_kstep(acc, aB, bB, 0, m0w, n0w, lr, lc);
        mma_kstep(acc, aB, bB, 16, m0w, n0w, lr, lc);
        mma_kstep(acc, aB, bB, 32, m0w, n0w, lr, lc);
        mma_kstep(acc, aB, bB, 48, m0w, n0w, lr, lc);
        CP_WAIT0();
        __syncthreads();
    }

    int rq = l >> 2, cq = (l & 3) * 2;
#pragma unroll
    for (int mi = 0; mi < 4; mi++) {
        int rl = m0w + mi * 16 + rq;
        int grow = rowBase + rl;
#pragma unroll
        for (int ni = 0; ni < 8; ni++) {
            int gcol = d0 + n0w + ni * 8 + cq;
            float u0 = __ldg(&b2[gcol]), u1 = __ldg(&b2[gcol + 1]);
            float* a = acc[mi][ni];
            *(float2*)&out[(size_t)grow * 256 + gcol] =
                make_float2(gelu_f(a[0] + u0), gelu_f(a[1] + u1));
            *(float2*)&out[(size_t)(grow + 8) * 256 + gcol] =
                make_float2(gelu_f(a[2] + u0), gelu_f(a[3] + u1));
        }
    }
}

// ---------------- launch ----------------
extern "C" void kernel_launch(void* const* d_in, const int* in_sizes, int n_in,
                              void* d_out, int out_size) {
    const float* pt    = (const float*)d_in[0];
    const float* sh    = (const float*)d_in[1];
    const float* dyn   = (const float*)d_in[2];
    const float* sem   = (const float*)d_in[3];
    const float* pit   = (const float*)d_in[4];
    const float* rel   = (const float*)d_in[5];
    const float* vis   = (const float*)d_in[6];
    const float* gamma = (const float*)d_in[7];
    const float* beta  = (const float*)d_in[8];
    const float* W1    = (const float*)d_in[9];
    const float* b1    = (const float*)d_in[10];
    const float* W2    = (const float*)d_in[11];
    const float* b2    = (const float*)d_in[12];
    float* out = (float*)d_out;

    cudaFuncSetAttribute(gemm1, cudaFuncAttributeMaxDynamicSharedMemorySize, SMEM_DYN);
    cudaFuncSetAttribute(gemm2, cudaFuncAttributeMaxDynamicSharedMemorySize, SMEM_DYN);

    prep_w1<<<KPAD1, 256>>>(W1, gamma);
    prep_vu_part<<<16, 256>>>(W1, gamma, beta);
    prep_w2_vu<<<257, 256>>>(W2, b1);
    gemm1<<<dim3(2, 512), 128, SMEM_DYN>>>(pt, sh, dyn, sem, pit, rel, vis);
    gemm2<<<dim3(2, 512), 128, SMEM_DYN>>>(b2, out);
}

// round 15
// speedup vs baseline: 1.4010x; 1.4010x over previous
#include <cuda_runtime.h>
#include <cuda_fp16.h>
#include <cstdint>

#define NCH1 21                 // K1 = 1283 -> 21 chunks of 64
#define NCH2 4                  // K2 = 256  -> 4 chunks of 64
#define KPAD1 1344
#define INV_CAT (1.0f/1283.0f)

// smem (bytes): A stage s at s*18432 (128 rows x 144B, col-xor swizzled)
//               B stage s at 36864 + s*17408 (64 rows x 272B, col-xor swizzled), 3 stages
#define A_ST   18432
#define B_BASE 36864
#define B_ST   17408
#define SMEM_DYN (B_BASE + 3*B_ST)   // 89088 ; x2 CTAs = 178 KB/SM

// ---------------- scratch (no cudaMalloc allowed) ----------------
__device__ __align__(16) __half g_y1[65536u*256];
__device__ __align__(16) __half g_B1h[KPAD1*256];
__device__ __align__(16) __half g_B2h[256*256];
__device__ float g_v[256];
__device__ float g_u[256];
__device__ float g_part[16*512];

// ---------------- helpers ----------------
__device__ __forceinline__ uint32_t smem_u32(const void* p) {
    uint32_t a;
    asm("{ .reg .u64 t; cvta.to.shared.u64 t, %1; cvt.u32.u64 %0, t; }" : "=r"(a) : "l"(p));
    return a;
}
#define CP_A16(dst, src) \
    asm volatile("cp.async.cg.shared.global [%0], [%1], 16;" :: "r"(dst), "l"(src) : "memory")
#define CP_COMMIT() asm volatile("cp.async.commit_group;" ::: "memory")
#define CP_WAIT0()  asm volatile("cp.async.wait_group 0;" ::: "memory")
#define CP_WAIT1()  asm volatile("cp.async.wait_group 1;" ::: "memory")

__device__ __forceinline__ void ldsm_x4(uint32_t* f, uint32_t a) {
    asm volatile("ldmatrix.sync.aligned.m8n8.x4.shared.b16 {%0,%1,%2,%3}, [%4];"
                 : "=r"(f[0]), "=r"(f[1]), "=r"(f[2]), "=r"(f[3]) : "r"(a));
}
__device__ __forceinline__ void ldsm_x4t(uint32_t* f, uint32_t a) {
    asm volatile("ldmatrix.sync.aligned.m8n8.x4.trans.shared.b16 {%0,%1,%2,%3}, [%4];"
                 : "=r"(f[0]), "=r"(f[1]), "=r"(f[2]), "=r"(f[3]) : "r"(a));
}
__device__ __forceinline__ void mma16816(float* c, const uint32_t* a, uint32_t b0, uint32_t b1) {
    asm volatile("mma.sync.aligned.m16n8k16.row.col.f32.f16.f16.f32 "
                 "{%0,%1,%2,%3}, {%4,%5,%6,%7}, {%8,%9}, {%0,%1,%2,%3};"
                 : "+f"(c[0]), "+f"(c[1]), "+f"(c[2]), "+f"(c[3])
                 : "r"(a[0]), "r"(a[1]), "r"(a[2]), "r"(a[3]), "r"(b0), "r"(b1));
}
__device__ __forceinline__ float gelu_f(float x) {
    return 0.5f * x * (1.0f + erff(x * 0.70710678118654752f));
}
__device__ __forceinline__ uint32_t pack_h2(float a, float b) {
    __half2 h = __floats2half2_rn(a, b);
    return *reinterpret_cast<uint32_t*>(&h);
}

// one k-step (K=16): 4 A-ldsm + 2 B-ldsm + 16 MMAs (warptile 64M x 32N)
// A: rows stride 144B, col byte = (kk+lc)*2 ^ ((lr&8)<<2)
// B: rows stride 272B, col byte = (ncol)*2   ^ ((lr&8)<<4)
__device__ __forceinline__ void mma_kstep(float (&acc)[4][4][4],
                                          uint32_t aB, uint32_t bB, int kk,
                                          int m0w, int n0w, int lr, int lc) {
    int ax = (lr & 8) << 2;
    int bx = (lr & 8) << 4;
    uint32_t ah[4][4], b[2][4];
    int acol = ((kk + lc) * 2) ^ ax;
#pragma unroll
    for (int mi = 0; mi < 4; mi++) {
        uint32_t off = (uint32_t)((m0w + mi * 16 + lr) * 144 + acol);
        ldsm_x4(ah[mi], aB + off);
    }
    int brow = (kk + lr) * 272;
#pragma unroll
    for (int np = 0; np < 2; np++) {
        int bcol = ((n0w + np * 16 + lc) * 2) ^ bx;
        ldsm_x4t(b[np], bB + (uint32_t)(brow + bcol));
    }
#pragma unroll
    for (int np = 0; np < 2; np++)
#pragma unroll
        for (int mi = 0; mi < 4; mi++) {
            mma16816(acc[mi][np * 2],     ah[mi], b[np][0], b[np][1]);
            mma16816(acc[mi][np * 2 + 1], ah[mi], b[np][2], b[np][3]);
        }
}

// async-copy one 64x128 fp16 B chunk into stage s (col-xor swizzled); 256 threads
__device__ __forceinline__ void cpB(uint32_t smBase, int s, const __half* src, int t) {
    int row = t >> 2, cb = (t & 3) * 64;       // 64B per thread
    int bx = (row & 8) << 4;
    uint32_t d = smBase + B_BASE + s * B_ST + (uint32_t)(row * 272);
    const char* sp = (const char*)(src + row * 256) + cb;
#pragma unroll
    for (int j = 0; j < 4; j++) CP_A16(d + (uint32_t)((cb + j * 16) ^ bx), sp + j * 16);
}

// load 16 fp32 cols at absolute col c0 for row r
__device__ __forceinline__ void load_x16(const float* const* seg,
                                         const float* rel, const float* vis,
                                         int r, int c0, float* x) {
    if (c0 < 1280) {
        const float* p = seg[c0 >> 8] + (c0 & 255);
#pragma unroll
        for (int j = 0; j < 4; j++) {
            float4 f = ((const float4*)p)[j];
            x[4 * j] = f.x; x[4 * j + 1] = f.y; x[4 * j + 2] = f.z; x[4 * j + 3] = f.w;
        }
    } else {
#pragma unroll
        for (int j = 0; j < 16; j++) x[j] = 0.f;
        if (c0 == 1280) {
            x[0] = rel[(size_t)r * 2];
            x[1] = rel[(size_t)r * 2 + 1];
            x[2] = vis[r];
        }
    }
}

// pack 16 cols -> 8 half2, store into A stage s at (row, half, part), swizzled
__device__ __forceinline__ void packA(char* sm, int s, int row, int half, int part,
                                      const float* x, float& sum, float& ss) {
    uint32_t hp[8];
#pragma unroll
    for (int j = 0; j < 8; j++) {
        float a = x[2 * j], b = x[2 * j + 1];
        sum += a + b; ss = fmaf(a, a, ss); ss = fmaf(b, b, ss);
        hp[j] = pack_h2(a, b);
    }
    int ax = (row & 8) << 2;
    int col = half * 64 + part * 32;
    char* rb = sm + s * A_ST + (uint32_t)(row * 144);
    *(uint4*)(rb + (col ^ ax))        = make_uint4(hp[0], hp[1], hp[2], hp[3]);
    *(uint4*)(rb + ((col + 16) ^ ax)) = make_uint4(hp[4], hp[5], hp[6], hp[7]);
}

// ---------------- prep kernels (3 launches before gemm1) ----------------
__global__ void prep_w1(const float* __restrict__ W1, const float* __restrict__ gamma) {
    int c = blockIdx.x, d = threadIdx.x;
    float w = (c < 1283) ? W1[(size_t)c * 256 + d] * gamma[c] : 0.0f;
    g_B1h[(size_t)c * 256 + d] = __float2half_rn(w);
}
__global__ void prep_vu_part(const float* __restrict__ W1, const float* __restrict__ gamma,
                             const float* __restrict__ beta) {
    int b = blockIdx.x, d = threadIdx.x;
    int c0 = b * 81, c1 = c0 + 81; if (c1 > 1283) c1 = 1283;
    float v = 0.f, u = 0.f;
    for (int c = c0; c < c1; c++) {
        float w = W1[(size_t)c * 256 + d];
        v += gamma[c] * w;
        u += beta[c] * w;
    }
    g_part[b * 512 + d] = v;
    g_part[b * 512 + 256 + d] = u;
}
__global__ void prep_w2_vu(const float* __restrict__ W2, const float* __restrict__ b1) {
    int d = threadIdx.x;
    if (blockIdx.x < 256) {
        int c = blockIdx.x;
        g_B2h[(size_t)c * 256 + d] = __float2half_rn(W2[(size_t)c * 256 + d]);
    } else {
        float v = 0.f, u = 0.f;
#pragma unroll
        for (int b = 0; b < 16; b++) {
            v += g_part[b * 512 + d];
            u += g_part[b * 512 + 256 + d];
        }
        g_v[d] = v;
        g_u[d] = u + b1[d];
    }
}

// ---------------- GEMM1: raw concat-x @ W1g, LN-folded epilogue + GELU -> g_y1 ----------------
__global__ __launch_bounds__(256, 2) void gemm1(
    const float* __restrict__ pt, const float* __restrict__ sh,
    const float* __restrict__ dyn, const float* __restrict__ sem,
    const float* __restrict__ pit, const float* __restrict__ rel,
    const float* __restrict__ vis, const float* __restrict__ b1) {
    extern __shared__ char sm[];
    __shared__ float s_sum[128], s_ss[128], s_v[256], s_u[256];

    int t = threadIdx.x, l = t & 31, wid = t >> 5;
    int m0w = (wid >> 2) * 64, n0w = (wid & 3) * 32;
    int lr = l & 15, lc = (l & 16) >> 1;
    int d0 = blockIdx.x * 128, rowBase = blockIdx.y * 128;
    int half = t & 1, row = t >> 1;
    int r = rowBase + row;
    int b_ = r >> 14, m_ = (r >> 6) & 255, h_ = r & 63;
    const float* seg[5] = { pt + (size_t)((b_ << 8) + m_) * 256,
                            sh + (size_t)((b_ << 6) + h_) * 256,
                            dyn + (size_t)r * 256,
                            sem + (size_t)r * 256,
                            pit + (size_t)r * 256 };
    uint32_t base = smem_u32(sm);
    int cbase = half * 32;

    // inline v/u final reduce
    {
        float v = 0.f, u = 0.f;
#pragma unroll
        for (int b = 0; b < 16; b++) {
            v += g_part[b * 512 + t];
            u += g_part[b * 512 + 256 + t];
        }
        s_v[t] = v;
        s_u[t] = u + b1[t];
    }

    float acc[4][4][4];
#pragma unroll
    for (int i = 0; i < 4; i++)
#pragma unroll
        for (int j = 0; j < 4; j++)
#pragma unroll
            for (int k = 0; k < 4; k++) acc[i][j][k] = 0.f;
    float sum = 0.f, ss = 0.f;
    float xa[16], xb[16];

    // ---- prologue: B0, B1 in flight; stage A0 ----
    cpB(base, 0, g_B1h + d0, t);
    CP_COMMIT();
    cpB(base, 1, g_B1h + 16384 + d0, t);
    CP_COMMIT();
    load_x16(seg, rel, vis, r, cbase, xa);
    load_x16(seg, rel, vis, r, cbase + 16, xb);
    packA(sm, 0, row, half, 0, xa, sum, ss);
    packA(sm, 0, row, half, 1, xb, sum, ss);
    CP_WAIT1();                 // B0 complete; B1 may fly
    __syncthreads();

    int sB = 0, nB = 2;
    for (int c = 0; c < NCH1; c++) {
        int sA = c & 1, nsA = sA ^ 1;
        bool more = (c + 1 < NCH1);
        bool pre  = (c + 2 < NCH1);
        uint32_t aB = base + sA * A_ST, bB = base + B_BASE + sB * B_ST;
        if (pre) {
            cpB(base, nB, g_B1h + (size_t)(c + 2) * 16384 + d0, t);
            CP_COMMIT();
        }
        if (more) load_x16(seg, rel, vis, r, (c + 1) * 64 + cbase, xa);
        mma_kstep(acc, aB, bB, 0, m0w, n0w, lr, lc);
        mma_kstep(acc, aB, bB, 16, m0w, n0w, lr, lc);
        if (more) {
            load_x16(seg, rel, vis, r, (c + 1) * 64 + cbase + 16, xb);
            packA(sm, nsA, row, half, 0, xa, sum, ss);
        }
        mma_kstep(acc, aB, bB, 32, m0w, n0w, lr, lc);
        mma_kstep(acc, aB, bB, 48, m0w, n0w, lr, lc);
        if (more) packA(sm, nsA, row, half, 1, xb, sum, ss);
        if (pre) CP_WAIT1(); else CP_WAIT0();
        __syncthreads();
        sB = (sB + 1 == 3) ? 0 : sB + 1;
        nB = (nB + 1 == 3) ? 0 : nB + 1;
    }

    // ---- row stats (2 threads per row) ----
    sum += __shfl_xor_sync(0xffffffffu, sum, 1);
    ss  += __shfl_xor_sync(0xffffffffu, ss, 1);
    if (!half) { s_sum[row] = sum; s_ss[row] = ss; }
    __syncthreads();

    // ---- epilogue: LN correction + GELU -> fp16 y1 ----
    int rq = l >> 2, cq = (l & 3) * 2;
#pragma unroll
    for (int mi = 0; mi < 4; mi++) {
        int rl = m0w + mi * 16 + rq;
        float mu0 = s_sum[rl] * INV_CAT;
        float rs0 = rsqrtf(fmaf(-mu0, mu0, s_ss[rl] * INV_CAT) + 1e-5f);
        float mu1 = s_sum[rl + 8] * INV_CAT;
        float rs1 = rsqrtf(fmaf(-mu1, mu1, s_ss[rl + 8] * INV_CAT) + 1e-5f);
        int grow = rowBase + rl;
#pragma unroll
        for (int ni = 0; ni < 4; ni++) {
            int lcol = d0 + n0w + ni * 8 + cq;     // d0 in {0,128} -> direct s_v index
            float v0 = s_v[lcol], v1 = s_v[lcol + 1];
            float u0 = s_u[lcol], u1 = s_u[lcol + 1];
            float* a = acc[mi][ni];
            float y0 = gelu_f(fmaf(rs0, a[0] - mu0 * v0, u0));
            float y1 = gelu_f(fmaf(rs0, a[1] - mu0 * v1, u1));
            float y2 = gelu_f(fmaf(rs1, a[2] - mu1 * v0, u0));
            float y3 = gelu_f(fmaf(rs1, a[3] - mu1 * v1, u1));
            *(uint32_t*)&g_y1[(size_t)grow * 256 + lcol] = pack_h2(y0, y1);
            *(uint32_t*)&g_y1[(size_t)(grow + 8) * 256 + lcol] = pack_h2(y2, y3);
        }
    }
}

// ---------------- GEMM2: y1 @ W2 + b2, GELU -> out ----------------
__global__ __launch_bounds__(256, 2) void gemm2(const float* __restrict__ b2,
                                                float* __restrict__ out) {
    extern __shared__ char sm[];
    __shared__ float s_b[256];
    int t = threadIdx.x, l = t & 31, wid = t >> 5;
    int m0w = (wid >> 2) * 64, n0w = (wid & 3) * 32;
    int lr = l & 15, lc = (l & 16) >> 1;
    int d0 = blockIdx.x * 128, rowBase = blockIdx.y * 128;
    int half = t & 1, row = t >> 1;
    int r = rowBase + row;
    uint32_t base = smem_u32(sm);

    s_b[t] = b2[t];

    float acc[4][4][4];
#pragma unroll
    for (int i = 0; i < 4; i++)
#pragma unroll
        for (int j = 0; j < 4; j++)
#pragma unroll
            for (int k = 0; k < 4; k++) acc[i][j][k] = 0.f;

    const char* ybase = (const char*)(g_y1 + (size_t)r * 256 + half * 32);
    int ax = (row & 8) << 2;
    int acolb = half * 64;
    uint32_t arow = base + (uint32_t)(row * 144);

    // prologue: groups B0; A0; B1  -> wait_group 1 leaves only B1 outstanding
    cpB(base, 0, g_B2h + d0, t);
    CP_COMMIT();
#pragma unroll
    for (int j = 0; j < 4; j++)
        CP_A16(arow + (uint32_t)((acolb + j * 16) ^ ax), ybase + j * 16);
    CP_COMMIT();
    cpB(base, 1, g_B2h + 16384 + d0, t);
    CP_COMMIT();
    CP_WAIT1();
    __syncthreads();

    int sB = 0, nB = 2;
    for (int c = 0; c < NCH2; c++) {
        int sA = c & 1, nsA = sA ^ 1;
        bool more = (c + 1 < NCH2);
        bool pre  = (c + 2 < NCH2);
        uint32_t aB = base + sA * A_ST, bB = base + B_BASE + sB * B_ST;
        if (more) {
            const char* ysrc = ybase + (size_t)(c + 1) * 128;
            uint32_t ad = arow + (uint32_t)(nsA * A_ST);
#pragma unroll
            for (int j = 0; j < 4; j++)
                CP_A16(ad + (uint32_t)((acolb + j * 16) ^ ax), ysrc + j * 16);
            CP_COMMIT();
        }
        if (pre) {
            cpB(base, nB, g_B2h + (size_t)(c + 2) * 16384 + d0, t);
            CP_COMMIT();
        }
        mma_kstep(acc, aB, bB, 0, m0w, n0w, lr, lc);
        mma_kstep(acc, aB, bB, 16, m0w, n0w, lr, lc);
        mma_kstep(acc, aB, bB, 32, m0w, n0w, lr, lc);
        mma_kstep(acc, aB, bB, 48, m0w, n0w, lr, lc);
        if (pre) CP_WAIT1(); else CP_WAIT0();
        __syncthreads();
        sB = (sB + 1 == 3) ? 0 : sB + 1;
        nB = (nB + 1 == 3) ? 0 : nB + 1;
    }

    int rq = l >> 2, cq = (l & 3) * 2;
#pragma unroll
    for (int mi = 0; mi < 4; mi++) {
        int rl = m0w + mi * 16 + rq;
        int grow = rowBase + rl;
#pragma unroll
        for (int ni = 0; ni < 4; ni++) {
            int gcol = d0 + n0w + ni * 8 + cq;
            int lcol = gcol & 255;
            float u0 = s_b[lcol], u1 = s_b[lcol + 1];
            float* a = acc[mi][ni];
            *(float2*)&out[(size_t)grow * 256 + gcol] =
                make_float2(gelu_f(a[0] + u0), gelu_f(a[1] + u1));
            *(float2*)&out[(size_t)(grow + 8) * 256 + gcol] =
                make_float2(gelu_f(a[2] + u0), gelu_f(a[3] + u1));
        }
    }
}

// ---------------- launch ----------------
extern "C" void kernel_launch(void* const* d_in, const int* in_sizes, int n_in,
                              void* d_out, int out_size) {
    const float* pt    = (const float*)d_in[0];
    const float* sh    = (const float*)d_in[1];
    const float* dyn   = (const float*)d_in[2];
    const float* sem   = (const float*)d_in[3];
    const float* pit   = (const float*)d_in[4];
    const float* rel   = (const float*)d_in[5];
    const float* vis   = (const float*)d_in[6];
    const float* gamma = (const float*)d_in[7];
    const float* beta  = (const float*)d_in[8];
    const float* W1    = (const float*)d_in[9];
    const float* b1    = (const float*)d_in[10];
    const float* W2    = (const float*)d_in[11];
    const float* b2    = (const float*)d_in[12];
    float* out = (float*)d_out;

    cudaFuncSetAttribute(gemm1, cudaFuncAttributeMaxDynamicSharedMemorySize, SMEM_DYN);
    cudaFuncSetAttribute(gemm2, cudaFuncAttributeMaxDynamicSharedMemorySize, SMEM_DYN);

    prep_w1<<<KPAD1, 256>>>(W1, gamma);
    prep_vu_part<<<16, 256>>>(W1, gamma, beta);
    prep_w2_vu<<<257, 256>>>(W2, b1);
    gemm1<<<dim3(2, 512), 256, SMEM_DYN>>>(pt, sh, dyn, sem, pit, rel, vis, b1);
    gemm2<<<dim3(2, 512), 256, SMEM_DYN>>>(b2, out);
}

// round 16
// speedup vs baseline: 1.6110x; 1.1499x over previous
#include <cuda_runtime.h>
#include <cuda_fp16.h>
#include <cstdint>

#define NCH1 21                 // K1 = 1283 -> 21 chunks of 64
#define NCH2 4                  // K2 = 256  -> 4 chunks of 64
#define KPAD1 1344
#define INV_CAT (1.0f/1283.0f)

// smem (bytes): A stage s at s*18432 (128 rows x 72 halves);
//               B stage s at 36864 + s*17408 (64 rows x 136 halves), 3 stages
#define A_ST   18432
#define B_BASE 36864
#define B_ST   17408
#define SMEM_DYN (B_BASE + 3*B_ST)   // 89088 ; x2 CTAs = 178 KB/SM

// ---------------- scratch (no cudaMalloc allowed) ----------------
__device__ __align__(16) __half g_y1[65536u*256];
__device__ __align__(16) __half g_B1h[KPAD1*256];
__device__ __align__(16) __half g_B2h[256*256];
__device__ float g_v[256];
__device__ float g_u[256];
__device__ float g_part[16*512];

// ---------------- helpers ----------------
__device__ __forceinline__ uint32_t smem_u32(const void* p) {
    uint32_t a;
    asm("{ .reg .u64 t; cvta.to.shared.u64 t, %1; cvt.u32.u64 %0, t; }" : "=r"(a) : "l"(p));
    return a;
}
#define CP_A16(dst, src) \
    asm volatile("cp.async.cg.shared.global [%0], [%1], 16;" :: "r"(dst), "l"(src) : "memory")
#define CP_COMMIT() asm volatile("cp.async.commit_group;" ::: "memory")
#define CP_WAIT0()  asm volatile("cp.async.wait_group 0;" ::: "memory")
#define CP_WAIT1()  asm volatile("cp.async.wait_group 1;" ::: "memory")

__device__ __forceinline__ void ldsm_x4(uint32_t* f, uint32_t a) {
    asm volatile("ldmatrix.sync.aligned.m8n8.x4.shared.b16 {%0,%1,%2,%3}, [%4];"
                 : "=r"(f[0]), "=r"(f[1]), "=r"(f[2]), "=r"(f[3]) : "r"(a));
}
__device__ __forceinline__ void ldsm_x4t(uint32_t* f, uint32_t a) {
    asm volatile("ldmatrix.sync.aligned.m8n8.x4.trans.shared.b16 {%0,%1,%2,%3}, [%4];"
                 : "=r"(f[0]), "=r"(f[1]), "=r"(f[2]), "=r"(f[3]) : "r"(a));
}
__device__ __forceinline__ void mma16816(float* c, const uint32_t* a, uint32_t b0, uint32_t b1) {
    asm volatile("mma.sync.aligned.m16n8k16.row.col.f32.f16.f16.f32 "
                 "{%0,%1,%2,%3}, {%4,%5,%6,%7}, {%8,%9}, {%0,%1,%2,%3};"
                 : "+f"(c[0]), "+f"(c[1]), "+f"(c[2]), "+f"(c[3])
                 : "r"(a[0]), "r"(a[1]), "r"(a[2]), "r"(a[3]), "r"(b0), "r"(b1));
}
__device__ __forceinline__ float gelu_f(float x) {
    return 0.5f * x * (1.0f + erff(x * 0.70710678118654752f));
}
__device__ __forceinline__ uint32_t pack_h2(float a, float b) {
    __half2 h = __floats2half2_rn(a, b);
    return *reinterpret_cast<uint32_t*>(&h);
}

// one k-step (K=16): 4 A-ldsm + 2 B-ldsm + 16 MMAs (warptile 64M x 32N)
__device__ __forceinline__ void mma_kstep(float (&acc)[4][4][4],
                                          uint32_t aB, uint32_t bB, int kk,
                                          int m0w, int n0w, int lr, int lc) {
    uint32_t ah[4][4], b[2][4];
#pragma unroll
    for (int mi = 0; mi < 4; mi++) {
        uint32_t off = (uint32_t)(((m0w + mi * 16 + lr) * 72 + kk + lc) * 2);
        ldsm_x4(ah[mi], aB + off);
    }
#pragma unroll
    for (int np = 0; np < 2; np++) {
        uint32_t boff = (uint32_t)(((kk + lr) * 136 + n0w + np * 16 + lc) * 2);
        ldsm_x4t(b[np], bB + boff);
    }
#pragma unroll
    for (int np = 0; np < 2; np++)
#pragma unroll
        for (int mi = 0; mi < 4; mi++) {
            mma16816(acc[mi][np * 2],     ah[mi], b[np][0], b[np][1]);
            mma16816(acc[mi][np * 2 + 1], ah[mi], b[np][2], b[np][3]);
        }
}

// async-copy one 64x128 fp16 B chunk into stage s; src pre-offset to chunk row 0 + d0
__device__ __forceinline__ void cpB(uint32_t smBase, int s, const __half* src, int t) {
    int row = t >> 2, colh = (t & 3) * 32;
    uint32_t d = smBase + B_BASE + s * B_ST + (uint32_t)(row * 136 + colh) * 2;
    const char* sp = (const char*)(src + row * 256 + colh);
    CP_A16(d, sp);       CP_A16(d + 16, sp + 16);
    CP_A16(d + 32, sp + 32); CP_A16(d + 48, sp + 48);
}

// load 16 fp32 cols at absolute col c0 for row r
__device__ __forceinline__ void load_x16(const float* const* seg,
                                         const float* rel, const float* vis,
                                         int r, int c0, float* x) {
    if (c0 < 1280) {
        const float* p = seg[c0 >> 8] + (c0 & 255);
#pragma unroll
        for (int j = 0; j < 4; j++) {
            float4 f = ((const float4*)p)[j];
            x[4 * j] = f.x; x[4 * j + 1] = f.y; x[4 * j + 2] = f.z; x[4 * j + 3] = f.w;
        }
    } else {
#pragma unroll
        for (int j = 0; j < 16; j++) x[j] = 0.f;
        if (c0 == 1280) {
            x[0] = rel[(size_t)r * 2];
            x[1] = rel[(size_t)r * 2 + 1];
            x[2] = vis[r];
        }
    }
}

// pack 16 cols -> 8 half2, store into A stage s at (row, half, part)
__device__ __forceinline__ void packA(char* sm, int s, int row, int half, int part,
                                      const float* x, float& sum, float& ss) {
    uint32_t hp[8];
#pragma unroll
    for (int j = 0; j < 8; j++) {
        float a = x[2 * j], b = x[2 * j + 1];
        sum += a + b; ss = fmaf(a, a, ss); ss = fmaf(b, b, ss);
        hp[j] = pack_h2(a, b);
    }
    char* da = sm + s * A_ST + (uint32_t)(row * 144 + half * 64 + part * 32);
    ((uint4*)da)[0] = make_uint4(hp[0], hp[1], hp[2], hp[3]);
    ((uint4*)da)[1] = make_uint4(hp[4], hp[5], hp[6], hp[7]);
}

// ---------------- prep kernels (3 launches before gemm1) ----------------
__global__ void prep_w1(const float* __restrict__ W1, const float* __restrict__ gamma) {
    int c = blockIdx.x, d = threadIdx.x;
    float w = (c < 1283) ? W1[(size_t)c * 256 + d] * gamma[c] : 0.0f;
    g_B1h[(size_t)c * 256 + d] = __float2half_rn(w);
}
__global__ void prep_vu_part(const float* __restrict__ W1, const float* __restrict__ gamma,
                             const float* __restrict__ beta) {
    int b = blockIdx.x, d = threadIdx.x;
    int c0 = b * 81, c1 = c0 + 81; if (c1 > 1283) c1 = 1283;
    float v = 0.f, u = 0.f;
    for (int c = c0; c < c1; c++) {
        float w = W1[(size_t)c * 256 + d];
        v += gamma[c] * w;
        u += beta[c] * w;
    }
    g_part[b * 512 + d] = v;
    g_part[b * 512 + 256 + d] = u;
}
__global__ void prep_w2_vu(const float* __restrict__ W2, const float* __restrict__ b1) {
    int d = threadIdx.x;
    if (blockIdx.x < 256) {
        int c = blockIdx.x;
        g_B2h[(size_t)c * 256 + d] = __float2half_rn(W2[(size_t)c * 256 + d]);
    } else {
        float v = 0.f, u = 0.f;
#pragma unroll
        for (int b = 0; b < 16; b++) {
            v += g_part[b * 512 + d];
            u += g_part[b * 512 + 256 + d];
        }
        g_v[d] = v;
        g_u[d] = u + b1[d];
    }
}

// ---------------- GEMM1: raw concat-x @ W1g, LN-folded epilogue + GELU -> g_y1 ----------------
__global__ __launch_bounds__(256, 2) void gemm1(
    const float* __restrict__ pt, const float* __restrict__ sh,
    const float* __restrict__ dyn, const float* __restrict__ sem,
    const float* __restrict__ pit, const float* __restrict__ rel,
    const float* __restrict__ vis, const float* __restrict__ b1) {
    extern __shared__ char sm[];
    __shared__ float s_sum[128], s_ss[128], s_v[256], s_u[256];

    int t = threadIdx.x, l = t & 31, wid = t >> 5;
    int m0w = (wid >> 2) * 64, n0w = (wid & 3) * 32;
    int lr = l & 15, lc = (l & 16) >> 1;
    int d0 = blockIdx.x * 128, rowBase = blockIdx.y * 128;
    int half = t & 1, row = t >> 1;
    int r = rowBase + row;
    int b_ = r >> 14, m_ = (r >> 6) & 255, h_ = r & 63;
    const float* seg[5] = { pt + (size_t)((b_ << 8) + m_) * 256,
                            sh + (size_t)((b_ << 6) + h_) * 256,
                            dyn + (size_t)r * 256,
                            sem + (size_t)r * 256,
                            pit + (size_t)r * 256 };
    uint32_t base = smem_u32(sm);
    int cbase = half * 32;   // this thread's first col within a chunk

    // inline v/u final reduce
    {
        float v = 0.f, u = 0.f;
#pragma unroll
        for (int b = 0; b < 16; b++) {
            v += g_part[b * 512 + t];
            u += g_part[b * 512 + 256 + t];
        }
        s_v[t] = v;
        s_u[t] = u + b1[t];
    }

    float acc[4][4][4];
#pragma unroll
    for (int i = 0; i < 4; i++)
#pragma unroll
        for (int j = 0; j < 4; j++)
#pragma unroll
            for (int k = 0; k < 4; k++) acc[i][j][k] = 0.f;
    float sum = 0.f, ss = 0.f;
    float xa[16], xb[16];

    // ---- prologue: B0, B1 in flight; stage A0 ----
    cpB(base, 0, g_B1h + d0, t);
    CP_COMMIT();
    cpB(base, 1, g_B1h + 16384 + d0, t);
    CP_COMMIT();
    load_x16(seg, rel, vis, r, cbase, xa);
    load_x16(seg, rel, vis, r, cbase + 16, xb);
    packA(sm, 0, row, half, 0, xa, sum, ss);
    packA(sm, 0, row, half, 1, xb, sum, ss);
    CP_WAIT1();                 // B0 complete; B1 still flying
    __syncthreads();

    int sB = 0, nB = 2;
    for (int c = 0; c < NCH1; c++) {
        int sA = c & 1, nsA = sA ^ 1;
        bool more = (c + 1 < NCH1);
        bool pre  = (c + 2 < NCH1);
        uint32_t aB = base + sA * A_ST, bB = base + B_BASE + sB * B_ST;
        if (pre) {
            cpB(base, nB, g_B1h + (size_t)(c + 2) * 16384 + d0, t);
            CP_COMMIT();
        }
        if (more) load_x16(seg, rel, vis, r, (c + 1) * 64 + cbase, xa);
        mma_kstep(acc, aB, bB, 0, m0w, n0w, lr, lc);
        mma_kstep(acc, aB, bB, 16, m0w, n0w, lr, lc);
        if (more) {
            load_x16(seg, rel, vis, r, (c + 1) * 64 + cbase + 16, xb);
            packA(sm, nsA, row, half, 0, xa, sum, ss);
        }
        mma_kstep(acc, aB, bB, 32, m0w, n0w, lr, lc);
        mma_kstep(acc, aB, bB, 48, m0w, n0w, lr, lc);
        if (more) packA(sm, nsA, row, half, 1, xb, sum, ss);
        if (pre) CP_WAIT1(); else CP_WAIT0();
        __syncthreads();
        sB = (sB + 1 == 3) ? 0 : sB + 1;
        nB = (nB + 1 == 3) ? 0 : nB + 1;
    }

    // ---- row stats (2 threads per row) ----
    sum += __shfl_xor_sync(0xffffffffu, sum, 1);
    ss  += __shfl_xor_sync(0xffffffffu, ss, 1);
    if (!half) { s_sum[row] = sum; s_ss[row] = ss; }
    __syncthreads();

    // ---- epilogue: LN correction + GELU -> fp16 y1 ----
    int rq = l >> 2, cq = (l & 3) * 2;
#pragma unroll
    for (int mi = 0; mi < 4; mi++) {
        int rl = m0w + mi * 16 + rq;
        float mu0 = s_sum[rl] * INV_CAT;
        float rs0 = rsqrtf(fmaf(-mu0, mu0, s_ss[rl] * INV_CAT) + 1e-5f);
        float mu1 = s_sum[rl + 8] * INV_CAT;
        float rs1 = rsqrtf(fmaf(-mu1, mu1, s_ss[rl + 8] * INV_CAT) + 1e-5f);
        int grow = rowBase + rl;
#pragma unroll
        for (int ni = 0; ni < 4; ni++) {
            int gcol = d0 + n0w + ni * 8 + cq;   // d0 in {0,128} -> direct index
            float v0 = s_v[gcol], v1 = s_v[gcol + 1];
            float u0 = s_u[gcol], u1 = s_u[gcol + 1];
            float* a = acc[mi][ni];
            float y0 = gelu_f(fmaf(rs0, a[0] - mu0 * v0, u0));
            float y1 = gelu_f(fmaf(rs0, a[1] - mu0 * v1, u1));
            float y2 = gelu_f(fmaf(rs1, a[2] - mu1 * v0, u0));
            float y3 = gelu_f(fmaf(rs1, a[3] - mu1 * v1, u1));
            *(uint32_t*)&g_y1[(size_t)grow * 256 + gcol] = pack_h2(y0, y1);
            *(uint32_t*)&g_y1[(size_t)(grow + 8) * 256 + gcol] = pack_h2(y2, y3);
        }
    }
}

// ---------------- GEMM2: y1 @ W2 + b2, GELU -> out ----------------
__global__ __launch_bounds__(256, 2) void gemm2(const float* __restrict__ b2,
                                                float* __restrict__ out) {
    extern __shared__ char sm[];
    __shared__ float s_b[256];
    int t = threadIdx.x, l = t & 31, wid = t >> 5;
    int m0w = (wid >> 2) * 64, n0w = (wid & 3) * 32;
    int lr = l & 15, lc = (l & 16) >> 1;
    int d0 = blockIdx.x * 128, rowBase = blockIdx.y * 128;
    int half = t & 1, row = t >> 1;
    int r = rowBase + row;
    uint32_t base = smem_u32(sm);

    s_b[t] = b2[t];

    float acc[4][4][4];
#pragma unroll
    for (int i = 0; i < 4; i++)
#pragma unroll
        for (int j = 0; j < 4; j++)
#pragma unroll
            for (int k = 0; k < 4; k++) acc[i][j][k] = 0.f;

    const char* ybase = (const char*)(g_y1 + (size_t)r * 256 + half * 32);
    uint32_t adst = base + (uint32_t)(row * 144 + half * 64);

    // prologue: groups B0; A0; B1  -> wait_group 1 leaves only B1 outstanding
    cpB(base, 0, g_B2h + d0, t);
    CP_COMMIT();
    CP_A16(adst, ybase);       CP_A16(adst + 16, ybase + 16);
    CP_A16(adst + 32, ybase + 32); CP_A16(adst + 48, ybase + 48);
    CP_COMMIT();
    cpB(base, 1, g_B2h + 16384 + d0, t);
    CP_COMMIT();
    CP_WAIT1();
    __syncthreads();

    int sB = 0, nB = 2;
    for (int c = 0; c < NCH2; c++) {
        int sA = c & 1, nsA = sA ^ 1;
        bool more = (c + 1 < NCH2);
        bool pre  = (c + 2 < NCH2);
        uint32_t aB = base + sA * A_ST, bB = base + B_BASE + sB * B_ST;
        if (more) {
            const char* ysrc = ybase + (size_t)(c + 1) * 128;
            uint32_t ad = adst + (uint32_t)(nsA * A_ST) - (uint32_t)(sA * 0);
            ad = base + (uint32_t)(nsA * A_ST + row * 144 + half * 64);
            CP_A16(ad, ysrc);       CP_A16(ad + 16, ysrc + 16);
            CP_A16(ad + 32, ysrc + 32); CP_A16(ad + 48, ysrc + 48);
            CP_COMMIT();
        }
        if (pre) {
            cpB(base, nB, g_B2h + (size_t)(c + 2) * 16384 + d0, t);
            CP_COMMIT();
        }
        mma_kstep(acc, aB, bB, 0, m0w, n0w, lr, lc);
        mma_kstep(acc, aB, bB, 16, m0w, n0w, lr, lc);
        mma_kstep(acc, aB, bB, 32, m0w, n0w, lr, lc);
        mma_kstep(acc, aB, bB, 48, m0w, n0w, lr, lc);
        if (pre) CP_WAIT1(); else CP_WAIT0();
        __syncthreads();
        sB = (sB + 1 == 3) ? 0 : sB + 1;
        nB = (nB + 1 == 3) ? 0 : nB + 1;
    }

    int rq = l >> 2, cq = (l & 3) * 2;
#pragma unroll
    for (int mi = 0; mi < 4; mi++) {
        int rl = m0w + mi * 16 + rq;
        int grow = rowBase + rl;
#pragma unroll
        for (int ni = 0; ni < 4; ni++) {
            int gcol = d0 + n0w + ni * 8 + cq;
            int lcol = gcol & 255;
            float u0 = s_b[lcol], u1 = s_b[lcol + 1];
            float* a = acc[mi][ni];
            *(float2*)&out[(size_t)grow * 256 + gcol] =
                make_float2(gelu_f(a[0] + u0), gelu_f(a[1] + u1));
            *(float2*)&out[(size_t)(grow + 8) * 256 + gcol] =
                make_float2(gelu_f(a[2] + u0), gelu_f(a[3] + u1));
        }
    }
}

// ---------------- launch ----------------
extern "C" void kernel_launch(void* const* d_in, const int* in_sizes, int n_in,
                              void* d_out, int out_size) {
    const float* pt    = (const float*)d_in[0];
    const float* sh    = (const float*)d_in[1];
    const float* dyn   = (const float*)d_in[2];
    const float* sem   = (const float*)d_in[3];
    const float* pit   = (const float*)d_in[4];
    const float* rel   = (const float*)d_in[5];
    const float* vis   = (const float*)d_in[6];
    const float* gamma = (const float*)d_in[7];
    const float* beta  = (const float*)d_in[8];
    const float* W1    = (const float*)d_in[9];
    const float* b1    = (const float*)d_in[10];
    const float* W2    = (const float*)d_in[11];
    const float* b2    = (const float*)d_in[12];
    float* out = (float*)d_out;

    cudaFuncSetAttribute(gemm1, cudaFuncAttributeMaxDynamicSharedMemorySize, SMEM_DYN);
    cudaFuncSetAttribute(gemm2, cudaFuncAttributeMaxDynamicSharedMemorySize, SMEM_DYN);

    prep_w1<<<KPAD1, 256>>>(W1, gamma);
    prep_vu_part<<<16, 256>>>(W1, gamma, beta);
    prep_w2_vu<<<257, 256>>>(W2, b1);
    gemm1<<<dim3(2, 512), 256, SMEM_DYN>>>(pt, sh, dyn, sem, pit, rel, vis, b1);
    gemm2<<<dim3(2, 512), 256, SMEM_DYN>>>(b2, out);
}

// round 17
// speedup vs baseline: 2.2464x; 1.3944x over previous
#include <cuda_runtime.h>
#include <cuda_fp16.h>
#include <cstdint>

#define NCH1 21                 // K1 = 1283 -> 21 chunks of 64
#define NCH2 4                  // K2 = 256  -> 4 chunks of 64
#define KPAD1 1344
#define INV_CAT (1.0f/1283.0f)

// smem (bytes): A stage s at s*18432 (128 rows x 72 halves, stride 144B);
//               B stage s at 36864 + s*17408 (64 rows x 136 halves, stride 272B)
#define A_ST   18432
#define B_BASE 36864
#define B_ST   17408
#define SMEM_DYN (B_BASE + 2*B_ST)   // 71680

// ---------------- scratch (no cudaMalloc allowed) ----------------
__device__ __align__(16) __half g_y1[65536u*256];
__device__ __align__(16) __half g_B1h[KPAD1*256];
__device__ __align__(16) __half g_B2h[256*256];
__device__ float g_part[16*512];

// ---------------- helpers ----------------
__device__ __forceinline__ uint32_t smem_u32(const void* p) {
    uint32_t a;
    asm("{ .reg .u64 t; cvta.to.shared.u64 t, %1; cvt.u32.u64 %0, t; }" : "=r"(a) : "l"(p));
    return a;
}
#define CP_A16(dst, src) \
    asm volatile("cp.async.cg.shared.global [%0], [%1], 16;" :: "r"(dst), "l"(src) : "memory")
#define CP_COMMIT() asm volatile("cp.async.commit_group;" ::: "memory")
#define CP_WAIT0()  asm volatile("cp.async.wait_group 0;" ::: "memory")

__device__ __forceinline__ void ldsm_x4(uint32_t* f, uint32_t a) {
    asm volatile("ldmatrix.sync.aligned.m8n8.x4.shared.b16 {%0,%1,%2,%3}, [%4];"
                 : "=r"(f[0]), "=r"(f[1]), "=r"(f[2]), "=r"(f[3]) : "r"(a));
}
__device__ __forceinline__ void ldsm_x4t(uint32_t* f, uint32_t a) {
    asm volatile("ldmatrix.sync.aligned.m8n8.x4.trans.shared.b16 {%0,%1,%2,%3}, [%4];"
                 : "=r"(f[0]), "=r"(f[1]), "=r"(f[2]), "=r"(f[3]) : "r"(a));
}
__device__ __forceinline__ void mma16816(float* c, const uint32_t* a, uint32_t b0, uint32_t b1) {
    asm volatile("mma.sync.aligned.m16n8k16.row.col.f32.f16.f16.f32 "
                 "{%0,%1,%2,%3}, {%4,%5,%6,%7}, {%8,%9}, {%0,%1,%2,%3};"
                 : "+f"(c[0]), "+f"(c[1]), "+f"(c[2]), "+f"(c[3])
                 : "r"(a[0]), "r"(a[1]), "r"(a[2]), "r"(a[3]), "r"(b0), "r"(b1));
}
__device__ __forceinline__ float gelu_f(float x) {
    return 0.5f * x * (1.0f + erff(x * 0.70710678118654752f));
}
__device__ __forceinline__ uint32_t pack_h2(float a, float b) {
    __half2 h = __floats2half2_rn(a, b);
    return *reinterpret_cast<uint32_t*>(&h);
}

// one k-step (K=16): 4 A-ldsm + 2 B-ldsm + 16 MMAs (warptile 64M x 32N)
__device__ __forceinline__ void mma_kstep(float (&acc)[4][4][4],
                                          uint32_t aB, uint32_t bB, int kk,
                                          int m0w, int n0w, int lr, int lc) {
    uint32_t ah[4][4], b[2][4];
#pragma unroll
    for (int mi = 0; mi < 4; mi++) {
        uint32_t off = (uint32_t)(((m0w + mi * 16 + lr) * 72 + kk + lc) * 2);
        ldsm_x4(ah[mi], aB + off);
    }
#pragma unroll
    for (int np = 0; np < 2; np++) {
        uint32_t boff = (uint32_t)(((kk + lr) * 136 + n0w + np * 16 + lc) * 2);
        ldsm_x4t(b[np], bB + boff);
    }
#pragma unroll
    for (int np = 0; np < 2; np++)
#pragma unroll
        for (int mi = 0; mi < 4; mi++) {
            mma16816(acc[mi][np * 2],     ah[mi], b[np][0], b[np][1]);
            mma16816(acc[mi][np * 2 + 1], ah[mi], b[np][2], b[np][3]);
        }
}

// async-copy one 64x128 fp16 B chunk into stage s; src pre-offset to chunk row 0 + d0
__device__ __forceinline__ void cpB(uint32_t smBase, int s, const __half* src, int t) {
    int row = t >> 2, colh = (t & 3) * 32;
    uint32_t d = smBase + B_BASE + s * B_ST + (uint32_t)(row * 136 + colh) * 2;
    const char* sp = (const char*)(src + row * 256 + colh);
    CP_A16(d, sp);       CP_A16(d + 16, sp + 16);
    CP_A16(d + 32, sp + 32); CP_A16(d + 48, sp + 48);
}

// coalesced load of one half-chunk (32 cols) for this thread's 4 rows:
// thread handles rows r0..r0+3, cols 4j..4j+3 within the half.
// Lanes 0-7 cover one row's 32 cols contiguously -> 1 wavefront per 8-lane group.
__device__ __forceinline__ void load_half(const float* const* p, const float* rel,
                                          const float* vis, int r0, int j,
                                          int c, int h, float* x) {
    if (c < 20) {
        int s = c >> 2;
        const float* b = p[s] + (c & 3) * 64 + h * 32 + 4 * j;
        int rs = (s == 0) ? 0 : 256;   // pt is broadcast over the 4 rows
#pragma unroll
        for (int k = 0; k < 4; k++) {
            float4 f = *(const float4*)(b + k * rs);
            x[4 * k] = f.x; x[4 * k + 1] = f.y; x[4 * k + 2] = f.z; x[4 * k + 3] = f.w;
        }
    } else {
#pragma unroll
        for (int k = 0; k < 16; k++) x[k] = 0.f;
        if (j == 0 && h == 0) {
#pragma unroll
            for (int k = 0; k < 4; k++) {
                x[4 * k]     = rel[(size_t)(r0 + k) * 2];
                x[4 * k + 1] = rel[(size_t)(r0 + k) * 2 + 1];
                x[4 * k + 2] = vis[r0 + k];
            }
        }
    }
}

// pack a half (4 rows x 4 cols) into A stage s, accumulate per-row stats
__device__ __forceinline__ void stage_half(char* sm, int s, int r0, int j, int h,
                                           const float* x, float* sum, float* ss) {
    char* a16 = sm + s * A_ST;
    int colb = h * 64 + 8 * j;          // byte offset within row (cols*2)
#pragma unroll
    for (int k = 0; k < 4; k++) {
        float a = x[4 * k], b = x[4 * k + 1], c2 = x[4 * k + 2], d = x[4 * k + 3];
        sum[k] += (a + b) + (c2 + d);
        ss[k] = fmaf(a, a, ss[k]); ss[k] = fmaf(b, b, ss[k]);
        ss[k] = fmaf(c2, c2, ss[k]); ss[k] = fmaf(d, d, ss[k]);
        *(uint2*)(a16 + (uint32_t)((r0 + k) * 144 + colb)) =
            make_uint2(pack_h2(a, b), pack_h2(c2, d));
    }
}

// ---------------- prep kernels (3 launches before gemm1) ----------------
__global__ void prep_w1(const float* __restrict__ W1, const float* __restrict__ gamma) {
    int c = blockIdx.x, d = threadIdx.x;
    float w = (c < 1283) ? W1[(size_t)c * 256 + d] * gamma[c] : 0.0f;
    g_B1h[(size_t)c * 256 + d] = __float2half_rn(w);
}
__global__ void prep_vu_part(const float* __restrict__ W1, const float* __restrict__ gamma,
                             const float* __restrict__ beta) {
    int b = blockIdx.x, d = threadIdx.x;
    int c0 = b * 81, c1 = c0 + 81; if (c1 > 1283) c1 = 1283;
    float v = 0.f, u = 0.f;
    for (int c = c0; c < c1; c++) {
        float w = W1[(size_t)c * 256 + d];
        v += gamma[c] * w;
        u += beta[c] * w;
    }
    g_part[b * 512 + d] = v;
    g_part[b * 512 + 256 + d] = u;
}
__global__ void prep_w2(const float* __restrict__ W2) {
    int c = blockIdx.x, d = threadIdx.x;
    g_B2h[(size_t)c * 256 + d] = __float2half_rn(W2[(size_t)c * 256 + d]);
}

// ---------------- GEMM1: raw concat-x @ W1g, LN-folded epilogue + GELU -> g_y1 ----------------
__global__ __launch_bounds__(256, 2) void gemm1(
    const float* __restrict__ pt, const float* __restrict__ sh,
    const float* __restrict__ dyn, const float* __restrict__ sem,
    const float* __restrict__ pit, const float* __restrict__ rel,
    const float* __restrict__ vis, const float* __restrict__ b1) {
    extern __shared__ char sm[];
    __shared__ float s_sum[128], s_ss[128], s_v[256], s_u[256];

    int t = threadIdx.x, l = t & 31, wid = t >> 5;
    int m0w = (wid >> 2) * 64, n0w = (wid & 3) * 32;
    int lr = l & 15, lc = (l & 16) >> 1;
    int d0 = blockIdx.x * 128, rowBase = blockIdx.y * 128;
    // staging map: g = t>>3 (0..31), j = t&7; rows 4g..4g+3
    int g = t >> 3, j = t & 7;
    int r0l = 4 * g;                 // local row of first staged row
    int r0 = rowBase + r0l;
    int b_ = r0 >> 14, m_ = (r0 >> 6) & 255, h_ = r0 & 63;
    const float* seg[5] = { pt + (size_t)((b_ << 8) + m_) * 256,
                            sh + (size_t)((b_ << 6) + h_) * 256,
                            dyn + (size_t)r0 * 256,
                            sem + (size_t)r0 * 256,
                            pit + (size_t)r0 * 256 };
    uint32_t base = smem_u32(sm);

    // inline v/u final reduce
    {
        float v = 0.f, u = 0.f;
#pragma unroll
        for (int b = 0; b < 16; b++) {
            v += g_part[b * 512 + t];
            u += g_part[b * 512 + 256 + t];
        }
        s_v[t] = v;
        s_u[t] = u + b1[t];
    }

    float acc[4][4][4];
#pragma unroll
    for (int i = 0; i < 4; i++)
#pragma unroll
        for (int jj = 0; jj < 4; jj++)
#pragma unroll
            for (int k = 0; k < 4; k++) acc[i][jj][k] = 0.f;
    float sum[4] = {0.f, 0.f, 0.f, 0.f}, ss[4] = {0.f, 0.f, 0.f, 0.f};
    float x[16];

    // ---- prologue: stage chunk 0 ----
    cpB(base, 0, g_B1h + d0, t);
    CP_COMMIT();
    load_half(seg, rel, vis, r0, j, 0, 0, x);
    stage_half(sm, 0, r0l, j, 0, x, sum, ss);
    load_half(seg, rel, vis, r0, j, 0, 1, x);
    stage_half(sm, 0, r0l, j, 1, x, sum, ss);
    CP_WAIT0();
    __syncthreads();

    for (int c = 0; c < NCH1; c++) {
        int s = c & 1, ns = s ^ 1;
        bool more = (c + 1 < NCH1);
        uint32_t aB = base + s * A_ST, bB = base + B_BASE + s * B_ST;
        if (more) {
            load_half(seg, rel, vis, r0, j, c + 1, 0, x);
            cpB(base, ns, g_B1h + (size_t)(c + 1) * 16384 + d0, t);
            CP_COMMIT();
        }
        mma_kstep(acc, aB, bB, 0, m0w, n0w, lr, lc);
        mma_kstep(acc, aB, bB, 16, m0w, n0w, lr, lc);
        if (more) {
            stage_half(sm, ns, r0l, j, 0, x, sum, ss);
            load_half(seg, rel, vis, r0, j, c + 1, 1, x);
        }
        mma_kstep(acc, aB, bB, 32, m0w, n0w, lr, lc);
        mma_kstep(acc, aB, bB, 48, m0w, n0w, lr, lc);
        if (more) stage_half(sm, ns, r0l, j, 1, x, sum, ss);
        CP_WAIT0();
        __syncthreads();
    }

    // ---- row stats: reduce over 8 staging lanes per row ----
#pragma unroll
    for (int k = 0; k < 4; k++) {
        float s1 = sum[k], s2 = ss[k];
        s1 += __shfl_xor_sync(0xffffffffu, s1, 1);
        s2 += __shfl_xor_sync(0xffffffffu, s2, 1);
        s1 += __shfl_xor_sync(0xffffffffu, s1, 2);
        s2 += __shfl_xor_sync(0xffffffffu, s2, 2);
        s1 += __shfl_xor_sync(0xffffffffu, s1, 4);
        s2 += __shfl_xor_sync(0xffffffffu, s2, 4);
        if (j == 0) { s_sum[r0l + k] = s1; s_ss[r0l + k] = s2; }
    }
    __syncthreads();

    // ---- epilogue: LN correction + GELU -> fp16 y1 ----
    int rq = l >> 2, cq = (l & 3) * 2;
#pragma unroll
    for (int mi = 0; mi < 4; mi++) {
        int rl = m0w + mi * 16 + rq;
        float mu0 = s_sum[rl] * INV_CAT;
        float rs0 = rsqrtf(fmaf(-mu0, mu0, s_ss[rl] * INV_CAT) + 1e-5f);
        float mu1 = s_sum[rl + 8] * INV_CAT;
        float rs1 = rsqrtf(fmaf(-mu1, mu1, s_ss[rl + 8] * INV_CAT) + 1e-5f);
        int grow = rowBase + rl;
#pragma unroll
        for (int ni = 0; ni < 4; ni++) {
            int gcol = d0 + n0w + ni * 8 + cq;   // d0 in {0,128} -> direct index
            float v0 = s_v[gcol], v1 = s_v[gcol + 1];
            float u0 = s_u[gcol], u1 = s_u[gcol + 1];
            float* a = acc[mi][ni];
            float y0 = gelu_f(fmaf(rs0, a[0] - mu0 * v0, u0));
            float y1 = gelu_f(fmaf(rs0, a[1] - mu0 * v1, u1));
            float y2 = gelu_f(fmaf(rs1, a[2] - mu1 * v0, u0));
            float y3 = gelu_f(fmaf(rs1, a[3] - mu1 * v1, u1));
            *(uint32_t*)&g_y1[(size_t)grow * 256 + gcol] = pack_h2(y0, y1);
            *(uint32_t*)&g_y1[(size_t)(grow + 8) * 256 + gcol] = pack_h2(y2, y3);
        }
    }
}

// ---------------- GEMM2: y1 @ W2 + b2, GELU -> out ----------------
__global__ __launch_bounds__(256, 2) void gemm2(const float* __restrict__ b2,
                                                float* __restrict__ out) {
    extern __shared__ char sm[];
    __shared__ float s_b[256];
    int t = threadIdx.x, l = t & 31, wid = t >> 5;
    int m0w = (wid >> 2) * 64, n0w = (wid & 3) * 32;
    int lr = l & 15, lc = (l & 16) >> 1;
    int d0 = blockIdx.x * 128, rowBase = blockIdx.y * 128;
    int half = t & 1, row = t >> 1;
    int r = rowBase + row;
    uint32_t base = smem_u32(sm);

    s_b[t] = b2[t];

    float acc[4][4][4];
#pragma unroll
    for (int i = 0; i < 4; i++)
#pragma unroll
        for (int jj = 0; jj < 4; jj++)
#pragma unroll
            for (int k = 0; k < 4; k++) acc[i][jj][k] = 0.f;

    const char* ybase = (const char*)(g_y1 + (size_t)r * 256 + half * 32);
    uint32_t adst = base + (uint32_t)(row * 144 + half * 64);

    // prologue: stage chunk 0 via cp.async
    CP_A16(adst, ybase);       CP_A16(adst + 16, ybase + 16);
    CP_A16(adst + 32, ybase + 32); CP_A16(adst + 48, ybase + 48);
    cpB(base, 0, g_B2h + d0, t);
    CP_COMMIT();
    CP_WAIT0();
    __syncthreads();

    for (int c = 0; c < NCH2; c++) {
        int s = c & 1, ns = s ^ 1;
        bool more = (c + 1 < NCH2);
        uint32_t aB = base + s * A_ST, bB = base + B_BASE + s * B_ST;
        if (more) {
            const char* ysrc = ybase + (size_t)(c + 1) * 128;
            uint32_t ad = base + (uint32_t)(ns * A_ST + row * 144 + half * 64);
            CP_A16(ad, ysrc);       CP_A16(ad + 16, ysrc + 16);
            CP_A16(ad + 32, ysrc + 32); CP_A16(ad + 48, ysrc + 48);
            cpB(base, ns, g_B2h + (size_t)(c + 1) * 16384 + d0, t);
            CP_COMMIT();
        }
        mma_kstep(acc, aB, bB, 0, m0w, n0w, lr, lc);
        mma_kstep(acc, aB, bB, 16, m0w, n0w, lr, lc);
        mma_kstep(acc, aB, bB, 32, m0w, n0w, lr, lc);
        mma_kstep(acc, aB, bB, 48, m0w, n0w, lr, lc);
        CP_WAIT0();
        __syncthreads();
    }

    int rq = l >> 2, cq = (l & 3) * 2;
#pragma unroll
    for (int mi = 0; mi < 4; mi++) {
        int rl = m0w + mi * 16 + rq;
        int grow = rowBase + rl;
#pragma unroll
        for (int ni = 0; ni < 4; ni++) {
            int gcol = d0 + n0w + ni * 8 + cq;
            int lcol = gcol & 255;
            float u0 = s_b[lcol], u1 = s_b[lcol + 1];
            float* a = acc[mi][ni];
            *(float2*)&out[(size_t)grow * 256 + gcol] =
                make_float2(gelu_f(a[0] + u0), gelu_f(a[1] + u1));
            *(float2*)&out[(size_t)(grow + 8) * 256 + gcol] =
                make_float2(gelu_f(a[2] + u0), gelu_f(a[3] + u1));
        }
    }
}

// ---------------- launch ----------------
extern "C" void kernel_launch(void* const* d_in, const int* in_sizes, int n_in,
                              void* d_out, int out_size) {
    const float* pt    = (const float*)d_in[0];
    const float* sh    = (const float*)d_in[1];
    const float* dyn   = (const float*)d_in[2];
    const float* sem   = (const float*)d_in[3];
    const float* pit   = (const float*)d_in[4];
    const float* rel   = (const float*)d_in[5];
    const float* vis   = (const float*)d_in[6];
    const float* gamma = (const float*)d_in[7];
    const float* beta  = (const float*)d_in[8];
    const float* W1    = (const float*)d_in[9];
    const float* b1    = (const float*)d_in[10];
    const float* W2    = (const float*)d_in[11];
    const float* b2    = (const float*)d_in[12];
    float* out = (float*)d_out;

    cudaFuncSetAttribute(gemm1, cudaFuncAttributeMaxDynamicSharedMemorySize, SMEM_DYN);
    cudaFuncSetAttribute(gemm2, cudaFuncAttributeMaxDynamicSharedMemorySize, SMEM_DYN);

    prep_w1<<<KPAD1, 256>>>(W1, gamma);
    prep_vu_part<<<16, 256>>>(W1, gamma, beta);
    prep_w2<<<256, 256>>>(W2);
    gemm1<<<dim3(2, 512), 256, SMEM_DYN>>>(pt, sh, dyn, sem, pit, rel, vis, b1);
    gemm2<<<dim3(2, 512), 256, SMEM_DYN>>>(b2, out);
}